// round 15
// baseline (speedup 1.0000x reference)
#include <cuda_runtime.h>
#include <math.h>

// Problem constants
#define B_   64
#define L_   512
#define D_   256
#define H_   256
#define T_   11
#define M_   (B_ * L_)      // 32768 rows (b*L + l)
#define G4H  (4 * H_)       // 1024 gate rows (i,f,g,o blocks of 256)

#define NBLK_LSTM 128       // persistent blocks (<=148 SMs, 1/SM)

// smem layout (floats)
#define OFF_W    0          // W_hh: 128 rows * 260
#define OFF_H    33280      // h: 8 * 260
#define OFF_G    35360      // G: 128 * 9 -> ends 36512
#define OFF_WHI  36512      // producer tiles: 32 k-rows * 136 (stride==8 mod 32)
#define OFF_WLO  40864
#define OFF_EHI  45216
#define OFF_ELO  49568
#define OFF_CNT  53920      // produced-group counter
#define SMEM_FLOATS 53924   // ~211 KB

#define BAR_C() asm volatile("bar.sync 1, 256;" ::: "memory")
#define BAR_P() asm volatile("bar.sync 2, 256;" ::: "memory")

// tf32 truncation (13 explicit mantissa bits kept)
__device__ __forceinline__ unsigned tf32_bits(float x) {
    return __float_as_uint(x) & 0xFFFFE000u;
}

// D = A*B + D, m16n8k8 tf32 (sm_80 baseline PTX — no 'a' target needed)
__device__ __forceinline__ void mma_tf32(float* c,
    unsigned a0, unsigned a1, unsigned a2, unsigned a3,
    unsigned b0, unsigned b1)
{
    asm volatile(
        "mma.sync.aligned.m16n8k8.row.col.f32.tf32.tf32.f32 "
        "{%0,%1,%2,%3}, {%4,%5,%6,%7}, {%8,%9}, {%0,%1,%2,%3};"
        : "+f"(c[0]), "+f"(c[1]), "+f"(c[2]), "+f"(c[3])
        : "r"(a0), "r"(a1), "r"(a2), "r"(a3), "r"(b0), "r"(b1));
}

// ---------------------------------------------------------------------------
// Scratch (static __device__ — no allocations allowed)
// ---------------------------------------------------------------------------
__device__ float g_gates[2 * 32768 * 1024];     // [dir][b*L+l][4H] input-proj + bias
__device__ float g_hseq[32768 * 512];           // [b*L+l][512] = concat(hf, hb)
__device__ float g_hbuf[2][2][B_ * H_];         // [dir][parity][b*H + j]
__device__ float g_logits[32768 * T_];          // [b*L+l][T]
__device__ unsigned int g_cnt[2][8];            // per-(dir, batch-group) h-completion

// ---------------------------------------------------------------------------
// Init: copy h0 into parity-0 h buffers, reset counters
// ---------------------------------------------------------------------------
__global__ void init_kernel(const float* __restrict__ h0) {
    int i = blockIdx.x * blockDim.x + threadIdx.x;
    if (i < 16) ((unsigned int*)g_cnt)[i] = 0u;
    if (i < 2 * B_ * H_) {
        int dir = i / (B_ * H_);
        int rem = i - dir * (B_ * H_);
        g_hbuf[dir][0][rem] = h0[i];
    }
}

// ---------------------------------------------------------------------------
// Fused persistent kernel.
//   warps 0-7  : producer — input projection via 3-term TF32 mma.sync
//                (Whi*Ehi + Whi*Elo + Wlo*Ehi; error ~2^-26, fp32-equivalent)
//   warps 8-15 : recurrence (R11 fp32 path, unchanged)
// Producer per 16-l group: C[128 gate-rows x 128 (b,l) cols] = W[128x256]E^T.
// Tiles staged in smem with row stride 136 floats (==8 mod 32) so all
// fragment gathers are bank-conflict-free.
// ---------------------------------------------------------------------------
__global__ __launch_bounds__(512, 1) void lstm_kernel(
    const float* __restrict__ c0,
    const float* __restrict__ Whh_f, const float* __restrict__ Whh_b,
    const int* __restrict__ sent, const float* __restrict__ emb,
    const float* __restrict__ Wih_f, const float* __restrict__ b_f,
    const float* __restrict__ Wih_b, const float* __restrict__ b_b)
{
    extern __shared__ float sm[];
    float4* Wsm4 = (float4*)(sm + OFF_W);          // 128 rows * 65 float4 (pad)
    float4* hsm4 = (float4*)(sm + OFF_H);          // 8 batches * 65 float4
    float*  Gsm  = sm + OFF_G;                     // 128 rows * 9 (pad)
    unsigned* WhiU = (unsigned*)(sm + OFF_WHI);
    unsigned* WloU = (unsigned*)(sm + OFF_WLO);
    unsigned* EhiU = (unsigned*)(sm + OFF_EHI);
    unsigned* EloU = (unsigned*)(sm + OFF_ELO);
    volatile unsigned int* prod = (volatile unsigned int*)(sm + OFF_CNT);

    const int tid = threadIdx.x;
    const int bid = blockIdx.x;
    const int dir = bid >> 6;
    const int sub = bid & 63;
    const int bg  = sub >> 3;              // batch group 0..7
    const int b0  = bg * 8;                // batch tile base
    const int j0  = (sub & 7) * 32;        // hidden tile base

    if (tid == 0) *prod = 0u;

    // Compute threads preload W_hh slice
    if (tid >= 256) {
        const int ctid = tid - 256;
        const float4* Wg4 = (const float4*)(dir ? Whh_b : Whh_f);
        for (int idx = ctid; idx < 128 * 64; idx += 256) {
            int r = idx >> 6, k4 = idx & 63;
            int g = r >> 5, jj = r & 31;
            Wsm4[r * 65 + k4] = Wg4[(size_t)(g * H_ + j0 + jj) * 64 + k4];
        }
    }
    __syncthreads();   // prod init + W_hh visible

    if (tid < 256) {
        // ================= PRODUCER (warps 0-7, TF32 mma) =================
        const float* Wih  = dir ? Wih_b : Wih_f;
        const float* bias = dir ? b_b  : b_f;
        float* outBase = g_gates + (size_t)dir * M_ * G4H;

        const int lane = tid & 31, warp = tid >> 5;
        const int gid = lane >> 2, tig = lane & 3;
        const int nb  = warp * 16;                  // gate-row strip base

        // staging mapping: thread stages column scol, k-half khalf
        const int scol  = tid & 127;
        const int khalf = tid >> 7;
        const int grow_scol = (scol >> 5) * H_ + j0 + (scol & 31);
        const float* wRowG = Wih + (size_t)grow_scol * D_;

        // epilogue rows for this lane
        const int n_lo = nb + gid, n_hi = nb + gid + 8;
        const int grow_lo = (n_lo >> 5) * H_ + j0 + (n_lo & 31);
        const int grow_hi = (n_hi >> 5) * H_ + j0 + (n_hi & 31);
        const float bias_lo = bias[grow_lo];
        const float bias_hi = bias[grow_hi];

        for (int g = 0; g < 32; g++) {
            const int lbase = (dir ? (31 - g) : g) * 16;
            const int sv = sent[(b0 + (scol & 7)) * L_ + lbase + (scol >> 3)];
            const float* eRowG = emb + (size_t)sv * D_;

            float cacc[16][4];
#pragma unroll
            for (int t = 0; t < 16; t++)
#pragma unroll
                for (int r = 0; r < 4; r++) cacc[t][r] = 0.f;

            for (int c8 = 0; c8 < 8; c8++) {
                // Stage this 32-k chunk (hi/lo split), tile layout [k][col]
#pragma unroll
                for (int q = 0; q < 4; q++) {
                    const int kk = c8 * 32 + khalf * 16 + q * 4;
                    const int krow = khalf * 16 + q * 4;
                    float4 w = *(const float4*)(wRowG + kk);
                    float4 e = *(const float4*)(eRowG + kk);
                    float wf[4] = {w.x, w.y, w.z, w.w};
                    float ef[4] = {e.x, e.y, e.z, e.w};
#pragma unroll
                    for (int i = 0; i < 4; i++) {
                        unsigned whb = tf32_bits(wf[i]);
                        unsigned wlb = tf32_bits(wf[i] - __uint_as_float(whb));
                        unsigned ehb = tf32_bits(ef[i]);
                        unsigned elb = tf32_bits(ef[i] - __uint_as_float(ehb));
                        int a = (krow + i) * 136 + scol;
                        WhiU[a] = whb; WloU[a] = wlb;
                        EhiU[a] = ehb; EloU[a] = elb;
                    }
                }
                BAR_P();

                // 4 k8-steps over this chunk
#pragma unroll
                for (int kc = 0; kc < 4; kc++) {
                    const int kr = kc * 8;
                    const int ra = (kr + tig) * 136;
                    const int rb = (kr + tig + 4) * 136;
                    unsigned ah0 = WhiU[ra + nb + gid];
                    unsigned ah1 = WhiU[ra + nb + gid + 8];
                    unsigned ah2 = WhiU[rb + nb + gid];
                    unsigned ah3 = WhiU[rb + nb + gid + 8];
                    unsigned al0 = WloU[ra + nb + gid];
                    unsigned al1 = WloU[ra + nb + gid + 8];
                    unsigned al2 = WloU[rb + nb + gid];
                    unsigned al3 = WloU[rb + nb + gid + 8];
#pragma unroll
                    for (int t = 0; t < 16; t++) {
                        unsigned bh0 = EhiU[ra + t * 8 + gid];
                        unsigned bh1 = EhiU[rb + t * 8 + gid];
                        unsigned bl0 = EloU[ra + t * 8 + gid];
                        unsigned bl1 = EloU[rb + t * 8 + gid];
                        mma_tf32(cacc[t], ah0, ah1, ah2, ah3, bh0, bh1);
                        mma_tf32(cacc[t], ah0, ah1, ah2, ah3, bl0, bl1);
                        mma_tf32(cacc[t], al0, al1, al2, al3, bh0, bh1);
                    }
                }
                BAR_P();
            }

            // Epilogue: C[n][m] -> gates[(b0+(m&7))*L + lbase+(m>>3)][grow(n)]
#pragma unroll
            for (int t = 0; t < 16; t++) {
                const int m0 = t * 8 + 2 * tig;
                const int m1 = m0 + 1;
                const size_t mc0 = (size_t)(b0 + (m0 & 7)) * L_ + (lbase + (m0 >> 3));
                const size_t mc1 = (size_t)(b0 + (m1 & 7)) * L_ + (lbase + (m1 >> 3));
                __stcg(outBase + mc0 * G4H + grow_lo, cacc[t][0] + bias_lo);
                __stcg(outBase + mc1 * G4H + grow_lo, cacc[t][1] + bias_lo);
                __stcg(outBase + mc0 * G4H + grow_hi, cacc[t][2] + bias_hi);
                __stcg(outBase + mc1 * G4H + grow_hi, cacc[t][3] + bias_hi);
            }
            __threadfence();      // gate stores visible before counter bump
            BAR_P();              // all producers done with this group
            if (tid == 0) *prod = (unsigned)(g + 1);
        }
        return;   // producers exit; compute warps continue alone
    }

    // ================= COMPUTE (warps 8-15, R11 path) =====================
    const int ctid = tid - 256;

    const int ub = ctid >> 5, ujj = ctid & 31;
    float c = c0[dir * B_ * H_ + (b0 + ub) * H_ + j0 + ujj];

    const int ks   = ctid & 7;
    const int tile = ctid >> 3;
    const int rt   = tile >> 1;
    const int bq   = tile & 1;
    const int ri_fin = ((ks & 1) << 2) | (ks & 2) | ((ks >> 2) & 1);
    const int row_fin = rt * 8 + ri_fin;
    const int grow_fin = (row_fin >> 5) * H_ + j0 + (row_fin & 31);

    const float* gatesD = g_gates + (size_t)dir * M_ * G4H;
    volatile unsigned int* cnt = &g_cnt[dir][bg];

    for (int t = 0; t < L_; t++) {
        const int l  = dir ? (L_ - 1 - t) : t;
        const float* hread  = g_hbuf[dir][t & 1];
        float*       hwrite = g_hbuf[dir][(t & 1) ^ 1];

        {
            const unsigned need = (unsigned)(t >> 4) + 1u;
            while (*prod < need) { __nanosleep(20); }
        }

        float gi[4];
#pragma unroll
        for (int bi = 0; bi < 4; bi++)
            gi[bi] = gatesD[(size_t)((b0 + bq * 4 + bi) * L_ + l) * G4H + grow_fin];

        if (t > 0) {
            const unsigned int need = 8u * (unsigned)t;
            while (*cnt < need) { __nanosleep(20); }
        }

        const float4* hr4 = (const float4*)hread;
        for (int i = ctid; i < 8 * 64; i += 256) {
            int r = i >> 6, c4 = i & 63;
            hsm4[r * 65 + c4] = __ldcg(&hr4[(b0 + r) * 64 + c4]);
        }
        BAR_C();

        float acc[32];
#pragma unroll
        for (int v = 0; v < 32; v++) acc[v] = 0.f;

#pragma unroll 2
        for (int kk = 0; kk < 8; kk++) {
            const int k4 = ks + kk * 8;
            float4 hv[4];
#pragma unroll
            for (int bi = 0; bi < 4; bi++)
                hv[bi] = hsm4[(bq * 4 + bi) * 65 + k4];
#pragma unroll
            for (int ri = 0; ri < 8; ri++) {
                float4 w = Wsm4[(rt * 8 + ri) * 65 + k4];
#pragma unroll
                for (int bi = 0; bi < 4; bi++) {
                    float a = acc[ri * 4 + bi];
                    a = fmaf(w.x, hv[bi].x, a);
                    a = fmaf(w.y, hv[bi].y, a);
                    a = fmaf(w.z, hv[bi].z, a);
                    a = fmaf(w.w, hv[bi].w, a);
                    acc[ri * 4 + bi] = a;
                }
            }
        }

#pragma unroll
        for (int s = 0; s < 3; s++) {
            const int half = 16 >> s;
            const bool up = (ks >> s) & 1;
#pragma unroll
            for (int i = 0; i < half; i++) {
                float send = up ? acc[i] : acc[i + half];
                float recv = __shfl_xor_sync(0xffffffffu, send, 1 << s);
                acc[i] = (up ? acc[i + half] : acc[i]) + recv;
            }
        }
#pragma unroll
        for (int bi = 0; bi < 4; bi++)
            Gsm[row_fin * 9 + bq * 4 + bi] = acc[bi] + gi[bi];
        BAR_C();

        float iv = Gsm[( 0 + ujj) * 9 + ub];
        float fv = Gsm[(32 + ujj) * 9 + ub];
        float gv = Gsm[(64 + ujj) * 9 + ub];
        float ov = Gsm[(96 + ujj) * 9 + ub];
        float si = __fdividef(1.f, 1.f + __expf(-iv));
        float sf = __fdividef(1.f, 1.f + __expf(-fv));
        float so = __fdividef(1.f, 1.f + __expf(-ov));
        c = sf * c + si * tanhf(gv);
        float h = so * tanhf(c);

        int bglob = b0 + ub;
        __stcg(&hwrite[bglob * H_ + j0 + ujj], h);
        __stcg(&g_hseq[(size_t)(bglob * L_ + l) * 512 + dir * H_ + j0 + ujj], h);

        BAR_C();
        if (ctid == 0) {
            __threadfence();
            atomicAdd(&g_cnt[dir][bg], 1u);
        }
    }
}

// ---------------------------------------------------------------------------
// Output projection: logits[m][t] = hseq[m] . W_out[t] + b_out[t]
// ---------------------------------------------------------------------------
__global__ __launch_bounds__(128) void logits_kernel(
    const float* __restrict__ Wout, const float* __restrict__ bout)
{
    __shared__ float Wo[T_ * 512];
    __shared__ float bo[T_];
    int tid = threadIdx.x;
    for (int i = tid; i < T_ * 512; i += 128) Wo[i] = Wout[i];
    if (tid < T_) bo[tid] = bout[tid];
    __syncthreads();

    int idx = blockIdx.x * 128 + tid;   // 0..32767
    const float4* h4 = (const float4*)(g_hseq + (size_t)idx * 512);
    float acc[T_];
#pragma unroll
    for (int t = 0; t < T_; t++) acc[t] = 0.f;

    for (int k4 = 0; k4 < 128; k4++) {
        float4 h = h4[k4];
#pragma unroll
        for (int t = 0; t < T_; t++) {
            float4 w = *(const float4*)&Wo[t * 512 + k4 * 4];
            acc[t] = fmaf(h.x, w.x, fmaf(h.y, w.y, fmaf(h.z, w.z, fmaf(h.w, w.w, acc[t]))));
        }
    }
#pragma unroll
    for (int t = 0; t < T_; t++)
        g_logits[(size_t)idx * T_ + t] = acc[t] + bo[t];
}

// ---------------------------------------------------------------------------
// Viterbi: one warp per batch (R11 version — fastest measured).
// ---------------------------------------------------------------------------
__global__ __launch_bounds__(32) void viterbi_kernel(
    const float* __restrict__ trans, float* scores, float* paths)
{
    __shared__ float lg[L_ * T_];
    __shared__ unsigned char bps[(L_ - 1) * T_];

    const int b = blockIdx.x;
    const int j = threadIdx.x;

    const float* src = g_logits + (size_t)b * L_ * T_;
    for (int i = j; i < L_ * T_; i += 32) lg[i] = src[i];

    const int jj = (j < T_) ? j : 0;
    float trC[T_];
#pragma unroll
    for (int i = 0; i < T_; i++) trC[i] = trans[i * T_ + jj];

    __syncwarp();
    float prev = (j < T_) ? lg[j] : -1e30f;

    for (int t = 1; t < L_; t++) {
        float v[T_];
#pragma unroll
        for (int i = 0; i < T_; i++)
            v[i] = __shfl_sync(0xffffffffu, prev, i) + trC[i];

        float mv[6]; int mi[6];
#pragma unroll
        for (int p = 0; p < 5; p++) {
            bool sel = v[2 * p + 1] > v[2 * p];
            mv[p] = sel ? v[2 * p + 1] : v[2 * p];
            mi[p] = sel ? 2 * p + 1 : 2 * p;
        }
        mv[5] = v[10]; mi[5] = 10;
        float nv[3]; int ni[3];
#pragma unroll
        for (int p = 0; p < 3; p++) {
            bool sel = mv[2 * p + 1] > mv[2 * p];
            nv[p] = sel ? mv[2 * p + 1] : mv[2 * p];
            ni[p] = sel ? mi[2 * p + 1] : mi[2 * p];
        }
        bool s01 = nv[1] > nv[0];
        float pv = s01 ? nv[1] : nv[0];
        int   pi = s01 ? ni[1] : ni[0];
        bool sf_ = nv[2] > pv;
        float best = sf_ ? nv[2] : pv;
        int   bp   = sf_ ? ni[2] : pi;

        prev = lg[t * T_ + jj] + best;
        if (j < T_) bps[(t - 1) * T_ + j] = (unsigned char)bp;
    }

    __syncwarp();
    if (j == 0) {
        float best = prev; int tag = 0;
#pragma unroll
        for (int i = 1; i < T_; i++) {
            float vi = __shfl_sync(0x7ffu, prev, i);
            if (vi > best) { best = vi; tag = i; }
        }
        if (scores) scores[b] = best;
        if (paths) {
            paths[b * L_ + (L_ - 1)] = (float)tag;
            int st = tag;
            for (int t = L_ - 2; t >= 0; t--) {
                st = bps[t * T_ + st];
                paths[b * L_ + t] = (float)st;
            }
        }
    } else if (j < T_) {
#pragma unroll
        for (int i = 1; i < T_; i++) __shfl_sync(0x7ffu, prev, i);
    }
}

// ---------------------------------------------------------------------------
// Launcher
// ---------------------------------------------------------------------------
extern "C" void kernel_launch(void* const* d_in, const int* in_sizes, int n_in,
                              void* d_out, int out_size)
{
    const int*   sent  = (const int*)  d_in[0];
    const float* emb   = (const float*)d_in[1];
    const float* Wih_f = (const float*)d_in[2];
    const float* Whh_f = (const float*)d_in[3];
    const float* b_f   = (const float*)d_in[4];
    const float* Wih_b = (const float*)d_in[5];
    const float* Whh_b = (const float*)d_in[6];
    const float* b_b   = (const float*)d_in[7];
    const float* Wout  = (const float*)d_in[8];
    const float* bout  = (const float*)d_in[9];
    const float* trans = (const float*)d_in[10];
    const float* h0    = (const float*)d_in[11];
    const float* c0    = (const float*)d_in[12];

    float* out = (float*)d_out;
    float* scores = nullptr;
    float* paths  = nullptr;
    if (out_size >= B_ + B_ * L_)      { scores = out; paths = out + B_; }
    else if (out_size == B_ * L_)      { paths = out; }
    else                               { scores = out; }

    // 1. init h buffers + counters
    init_kernel<<<128, 256>>>(h0);

    // 2. fused producer (TF32 mma.sync) + recurrence (~211 KB smem)
    const int smem_bytes = SMEM_FLOATS * (int)sizeof(float);
    cudaFuncSetAttribute(lstm_kernel, cudaFuncAttributeMaxDynamicSharedMemorySize, smem_bytes);
    lstm_kernel<<<NBLK_LSTM, 512, smem_bytes>>>(c0, Whh_f, Whh_b,
                                                sent, emb, Wih_f, b_f, Wih_b, b_b);

    // 3. output projection
    logits_kernel<<<M_ / 128, 128>>>(Wout, bout);

    // 4. Viterbi decode + write outputs
    viterbi_kernel<<<B_, 32>>>(trans, scores, paths);
}

// round 16
// speedup vs baseline: 1.0299x; 1.0299x over previous
#include <cuda_runtime.h>
#include <math.h>

// Problem constants
#define B_   64
#define L_   512
#define D_   256
#define H_   256
#define T_   11
#define M_   (B_ * L_)      // 32768 rows (b*L + l)
#define G4H  (4 * H_)       // 1024 gate rows (i,f,g,o blocks of 256)

#define NBLK_LSTM 128       // persistent blocks (<=148 SMs, 1/SM)

// smem layout (floats)
#define OFF_W    0          // W_hh: 128 rows * 260
#define OFF_H    33280      // h: 8 * 260
#define OFF_G    35360      // G: 128 * 9
#define OFF_WS   36512      // producer W tiles: 2 * 16 * 132
#define OFF_ES   40736      // producer E tiles: 2 * 16 * 132
#define OFF_CNT  44960      // produced-group counter
#define SMEM_FLOATS 44964

#define BAR_C() asm volatile("bar.sync 1, 256;" ::: "memory")
#define BAR_P() asm volatile("bar.sync 2, 256;" ::: "memory")

// Release-ordered counter bump: orders all prior stores before the add,
// without a full MEMBAR.GPU on the critical path.
__device__ __forceinline__ void red_release_add(unsigned int* p, unsigned v) {
    asm volatile("red.release.gpu.global.add.u32 [%0], %1;"
                 :: "l"(p), "r"(v) : "memory");
}

// ---------------------------------------------------------------------------
// Scratch (static __device__ — no allocations allowed)
// ---------------------------------------------------------------------------
__device__ float g_gates[2 * 32768 * 1024];     // [dir][b*L+l][4H] input-proj + bias
__device__ float g_hseq[32768 * 512];           // [b*L+l][512] = concat(hf, hb)
__device__ float g_hbuf[2][2][B_ * H_];         // [dir][parity][b*H + j]
__device__ float g_logits[32768 * T_];          // [b*L+l][T]
__device__ unsigned int g_cnt[2][8];            // per-(dir, batch-group) h-completion

// ---------------------------------------------------------------------------
// Init: copy h0 into parity-0 h buffers, reset counters
// ---------------------------------------------------------------------------
__global__ void init_kernel(const float* __restrict__ h0) {
    int i = blockIdx.x * blockDim.x + threadIdx.x;
    if (i < 16) ((unsigned int*)g_cnt)[i] = 0u;
    if (i < 2 * B_ * H_) {
        int dir = i / (B_ * H_);
        int rem = i - dir * (B_ * H_);
        g_hbuf[dir][0][rem] = h0[i];
    }
}

// ---------------------------------------------------------------------------
// Fused persistent kernel: producer warps (0-7) compute the input projection
// for THIS block's private gate slice; compute warps (8-15) run the
// recurrence.  Producer->consumer sync is a block-local smem counter over
// 16-l groups.  Cross-block h exchange via global monotonic counters with
// release-ordered publishes.
// ---------------------------------------------------------------------------
__global__ __launch_bounds__(512, 1) void lstm_kernel(
    const float* __restrict__ c0,
    const float* __restrict__ Whh_f, const float* __restrict__ Whh_b,
    const int* __restrict__ sent, const float* __restrict__ emb,
    const float* __restrict__ Wih_f, const float* __restrict__ b_f,
    const float* __restrict__ Wih_b, const float* __restrict__ b_b)
{
    extern __shared__ float sm[];
    float4* Wsm4 = (float4*)(sm + OFF_W);          // 128 rows * 65 float4 (pad)
    float4* hsm4 = (float4*)(sm + OFF_H);          // 8 batches * 65 float4
    float*  Gsm  = sm + OFF_G;                     // 128 rows * 9 (pad)
    float*  Ws   = sm + OFF_WS;                    // [buf][k=16][n=128 pad 132]
    float*  Es   = sm + OFF_ES;                    // [buf][k=16][m=128 pad 132]
    volatile unsigned int* prod = (volatile unsigned int*)(sm + OFF_CNT);

    const int tid = threadIdx.x;
    const int bid = blockIdx.x;
    const int dir = bid >> 6;
    const int sub = bid & 63;
    const int bg  = sub >> 3;              // batch group 0..7
    const int b0  = bg * 8;                // batch tile base
    const int j0  = (sub & 7) * 32;        // hidden tile base

    if (tid == 0) *prod = 0u;

    // Compute threads preload W_hh slice: smem row r -> gate g=r>>5, j0+(r&31)
    if (tid >= 256) {
        const int ctid = tid - 256;
        const float4* Wg4 = (const float4*)(dir ? Whh_b : Whh_f);
        for (int idx = ctid; idx < 128 * 64; idx += 256) {
            int r = idx >> 6, k4 = idx & 63;
            int g = r >> 5, jj = r & 31;
            Wsm4[r * 65 + k4] = Wg4[(size_t)(g * H_ + j0 + jj) * 64 + k4];
        }
    }
    __syncthreads();   // everyone: prod init + W_hh visible

    if (tid < 256) {
        // ================= PRODUCER (warps 0-7, low priority) =============
        const float* Wih  = dir ? Wih_b : Wih_f;
        const float* bias = dir ? b_b  : b_f;
        float* outBase = g_gates + (size_t)dir * M_ * G4H;

        const int n   = tid & 127;          // stage row id (gate-row / m index)
        const int kq  = tid >> 7;           // 0/1: which 8-k half this thread stages
        const int nt  = tid >> 4;           // 0..15: n-tile (8 rows)
        const int mt  = tid & 15;           // 0..15: m-tile (8 cols)

        const int gblk = n >> 5, jj = n & 31;
        const float* wRow = Wih + (size_t)(gblk * H_ + j0 + jj) * D_ + kq * 8;

        const int growN0 = (nt >> 2) * H_ + j0 + (nt & 3) * 8;   // first of 8 n-rows
        float bias8[8];
#pragma unroll
        for (int j = 0; j < 8; j++) bias8[j] = bias[growN0 + j];

        for (int g = 0; g < 32; g++) {
            const int lbase = (dir ? (31 - g) : g) * 16;

            const int sv = sent[(b0 + (n & 7)) * L_ + lbase + (n >> 3)];
            const float* eRow = emb + (size_t)sv * D_ + kq * 8;

            // Preload chunk 0 into buf 0
            {
                float4 w0 = *(const float4*)(wRow);
                float4 w1 = *(const float4*)(wRow + 4);
                float4 e0 = *(const float4*)(eRow);
                float4 e1 = *(const float4*)(eRow + 4);
                float* Wd = Ws + (kq * 8) * 132 + n;
                Wd[0*132]=w0.x; Wd[1*132]=w0.y; Wd[2*132]=w0.z; Wd[3*132]=w0.w;
                Wd[4*132]=w1.x; Wd[5*132]=w1.y; Wd[6*132]=w1.z; Wd[7*132]=w1.w;
                float* Ed = Es + (kq * 8) * 132 + n;
                Ed[0*132]=e0.x; Ed[1*132]=e0.y; Ed[2*132]=e0.z; Ed[3*132]=e0.w;
                Ed[4*132]=e1.x; Ed[5*132]=e1.y; Ed[6*132]=e1.z; Ed[7*132]=e1.w;
            }
            BAR_P();

            float acc[8][8];
#pragma unroll
            for (int i = 0; i < 8; i++)
#pragma unroll
                for (int j = 0; j < 8; j++) acc[i][j] = 0.f;

            for (int c = 0; c < 16; c++) {
                float4 nw0, nw1, ne0, ne1;
                if (c < 15) {
                    nw0 = *(const float4*)(wRow + (c + 1) * 16);
                    nw1 = *(const float4*)(wRow + (c + 1) * 16 + 4);
                    ne0 = *(const float4*)(eRow + (c + 1) * 16);
                    ne1 = *(const float4*)(eRow + (c + 1) * 16 + 4);
                }
                const float* Wb = Ws + (c & 1) * 2112;
                const float* Eb = Es + (c & 1) * 2112;
#pragma unroll
                for (int k = 0; k < 16; k++) {
                    float4 a0 = *(const float4*)(Wb + k * 132 + nt * 8);
                    float4 a1 = *(const float4*)(Wb + k * 132 + nt * 8 + 4);
                    float4 bb0 = *(const float4*)(Eb + k * 132 + mt * 8);
                    float4 bb1 = *(const float4*)(Eb + k * 132 + mt * 8 + 4);
                    float wv[8] = {a0.x,a0.y,a0.z,a0.w,a1.x,a1.y,a1.z,a1.w};
                    float ev[8] = {bb0.x,bb0.y,bb0.z,bb0.w,bb1.x,bb1.y,bb1.z,bb1.w};
#pragma unroll
                    for (int i = 0; i < 8; i++)
#pragma unroll
                        for (int j = 0; j < 8; j++)
                            acc[i][j] = fmaf(wv[i], ev[j], acc[i][j]);
                }
                if (c < 15) {
                    float* Wd = Ws + ((c + 1) & 1) * 2112 + (kq * 8) * 132 + n;
                    Wd[0*132]=nw0.x; Wd[1*132]=nw0.y; Wd[2*132]=nw0.z; Wd[3*132]=nw0.w;
                    Wd[4*132]=nw1.x; Wd[5*132]=nw1.y; Wd[6*132]=nw1.z; Wd[7*132]=nw1.w;
                    float* Ed = Es + ((c + 1) & 1) * 2112 + (kq * 8) * 132 + n;
                    Ed[0*132]=ne0.x; Ed[1*132]=ne0.y; Ed[2*132]=ne0.z; Ed[3*132]=ne0.w;
                    Ed[4*132]=ne1.x; Ed[5*132]=ne1.y; Ed[6*132]=ne1.z; Ed[7*132]=ne1.w;
                }
                BAR_P();
            }

            // Write out 8 m columns (each 8 consecutive gate rows)
#pragma unroll
            for (int j = 0; j < 8; j++) {
                int m = mt * 8 + j;
                int bi = m & 7, li = m >> 3;
                float* dst = outBase +
                    ((size_t)(b0 + bi) * L_ + (lbase + li)) * G4H + growN0;
                float4 o0 = make_float4(acc[0][j] + bias8[0], acc[1][j] + bias8[1],
                                        acc[2][j] + bias8[2], acc[3][j] + bias8[3]);
                float4 o1 = make_float4(acc[4][j] + bias8[4], acc[5][j] + bias8[5],
                                        acc[6][j] + bias8[6], acc[7][j] + bias8[7]);
                __stcg((float4*)dst, o0);
                __stcg((float4*)(dst + 4), o1);
            }
            __threadfence();      // my gate stores visible before counter bump
            BAR_P();              // all producers done with this group
            if (tid == 0) *prod = (unsigned)(g + 1);
        }
        return;   // producers exit; compute warps continue alone
    }

    // ================= COMPUTE (warps 8-15, high priority) ================
    const int ctid = tid - 256;

    // Cell-update thread mapping
    const int ub = ctid >> 5, ujj = ctid & 31;
    float c = c0[dir * B_ * H_ + (b0 + ub) * H_ + j0 + ujj];

    // GEMM thread mapping: 8-way interleaved k-split
    const int ks   = ctid & 7;
    const int tile = ctid >> 3;
    const int rt   = tile >> 1;            // 0..15 -> rows rt*8..rt*8+7
    const int bq   = tile & 1;             // batches bq*4..bq*4+3
    const int ri_fin = ((ks & 1) << 2) | (ks & 2) | ((ks >> 2) & 1);
    const int row_fin = rt * 8 + ri_fin;
    const int grow_fin = (row_fin >> 5) * H_ + j0 + (row_fin & 31);

    const float* gatesD = g_gates + (size_t)dir * M_ * G4H;
    volatile unsigned int* cnt = &g_cnt[dir][bg];

    for (int t = 0; t < L_; t++) {
        const int l  = dir ? (L_ - 1 - t) : t;
        const float* hread  = g_hbuf[dir][t & 1];
        float*       hwrite = g_hbuf[dir][(t & 1) ^ 1];

        // Wait for producer group covering this l
        {
            const unsigned need = (unsigned)(t >> 4) + 1u;
            while (*prod < need) { __nanosleep(20); }
        }

        // Prefetch input-projection preacts — in flight during h wait
        float gi[4];
#pragma unroll
        for (int bi = 0; bi < 4; bi++)
            gi[bi] = gatesD[(size_t)((b0 + bq * 4 + bi) * L_ + l) * G4H + grow_fin];

        // Wait for the 8 h-producers of this batch group (prev step)
        if (t > 0) {
            const unsigned int need = 8u * (unsigned)t;
            while (*cnt < need) { __nanosleep(20); }
        }

        // Stage previous h (8 batches x 256 units); L2-coherent loads
        const float4* hr4 = (const float4*)hread;
        for (int i = ctid; i < 8 * 64; i += 256) {
            int r = i >> 6, c4 = i & 63;
            hsm4[r * 65 + c4] = __ldcg(&hr4[(b0 + r) * 64 + c4]);
        }
        BAR_C();

        // 8x4 register-tiled GEMM, interleaved k-split (k4 = ks + 8*kk)
        float acc[32];
#pragma unroll
        for (int v = 0; v < 32; v++) acc[v] = 0.f;

#pragma unroll 2
        for (int kk = 0; kk < 8; kk++) {
            const int k4 = ks + kk * 8;
            float4 hv[4];
#pragma unroll
            for (int bi = 0; bi < 4; bi++)
                hv[bi] = hsm4[(bq * 4 + bi) * 65 + k4];
#pragma unroll
            for (int ri = 0; ri < 8; ri++) {
                float4 w = Wsm4[(rt * 8 + ri) * 65 + k4];
#pragma unroll
                for (int bi = 0; bi < 4; bi++) {
                    float a = acc[ri * 4 + bi];
                    a = fmaf(w.x, hv[bi].x, a);
                    a = fmaf(w.y, hv[bi].y, a);
                    a = fmaf(w.z, hv[bi].z, a);
                    a = fmaf(w.w, hv[bi].w, a);
                    acc[ri * 4 + bi] = a;
                }
            }
        }

        // K-split reduction: 3 butterfly rounds over lane bits 0..2 (ks)
#pragma unroll
        for (int s = 0; s < 3; s++) {
            const int half = 16 >> s;              // 16, 8, 4
            const bool up = (ks >> s) & 1;
#pragma unroll
            for (int i = 0; i < half; i++) {
                float send = up ? acc[i] : acc[i + half];
                float recv = __shfl_xor_sync(0xffffffffu, send, 1 << s);
                acc[i] = (up ? acc[i + half] : acc[i]) + recv;
            }
        }
#pragma unroll
        for (int bi = 0; bi < 4; bi++)
            Gsm[row_fin * 9 + bq * 4 + bi] = acc[bi] + gi[bi];
        BAR_C();

        // Gate nonlinearity + state update (PyTorch order i,f,g,o)
        float iv = Gsm[( 0 + ujj) * 9 + ub];
        float fv = Gsm[(32 + ujj) * 9 + ub];
        float gv = Gsm[(64 + ujj) * 9 + ub];
        float ov = Gsm[(96 + ujj) * 9 + ub];
        float si = __fdividef(1.f, 1.f + __expf(-iv));
        float sf = __fdividef(1.f, 1.f + __expf(-fv));
        float so = __fdividef(1.f, 1.f + __expf(-ov));
        c = sf * c + si * tanhf(gv);
        float h = so * tanhf(c);

        int bglob = b0 + ub;
        __stcg(&hwrite[bglob * H_ + j0 + ujj], h);
        __stcg(&g_hseq[(size_t)(bglob * L_ + l) * 512 + dir * H_ + j0 + ujj], h);

        // Publish: all h stores done -> release-ordered counter bump
        BAR_C();
        if (ctid == 0)
            red_release_add((unsigned int*)&g_cnt[dir][bg], 1u);
    }
}

// ---------------------------------------------------------------------------
// Output projection: logits[m][t] = hseq[m] . W_out[t] + b_out[t]
// 256 blocks x 128 threads: full SM coverage, 2 CTAs/SM to overlap the
// W_out smem stage with compute.
// ---------------------------------------------------------------------------
__global__ __launch_bounds__(128) void logits_kernel(
    const float* __restrict__ Wout, const float* __restrict__ bout)
{
    __shared__ float Wo[T_ * 512];
    __shared__ float bo[T_];
    int tid = threadIdx.x;
    for (int i = tid; i < T_ * 512; i += 128) Wo[i] = Wout[i];
    if (tid < T_) bo[tid] = bout[tid];
    __syncthreads();

    int idx = blockIdx.x * 128 + tid;   // 0..32767
    const float4* h4 = (const float4*)(g_hseq + (size_t)idx * 512);
    float acc[T_];
#pragma unroll
    for (int t = 0; t < T_; t++) acc[t] = 0.f;

    for (int k4 = 0; k4 < 128; k4++) {
        float4 h = h4[k4];
#pragma unroll
        for (int t = 0; t < T_; t++) {
            float4 w = *(const float4*)&Wo[t * 512 + k4 * 4];
            acc[t] = fmaf(h.x, w.x, fmaf(h.y, w.y, fmaf(h.z, w.z, fmaf(h.w, w.w, acc[t]))));
        }
    }
#pragma unroll
    for (int t = 0; t < T_; t++)
        g_logits[(size_t)idx * T_ + t] = acc[t] + bo[t];
}

// ---------------------------------------------------------------------------
// Viterbi: one warp per batch (R11 version — fastest measured).
// ---------------------------------------------------------------------------
__global__ __launch_bounds__(32) void viterbi_kernel(
    const float* __restrict__ trans, float* scores, float* paths)
{
    __shared__ float lg[L_ * T_];
    __shared__ unsigned char bps[(L_ - 1) * T_];

    const int b = blockIdx.x;
    const int j = threadIdx.x;

    const float* src = g_logits + (size_t)b * L_ * T_;
    for (int i = j; i < L_ * T_; i += 32) lg[i] = src[i];

    const int jj = (j < T_) ? j : 0;
    float trC[T_];
#pragma unroll
    for (int i = 0; i < T_; i++) trC[i] = trans[i * T_ + jj];

    __syncwarp();
    float prev = (j < T_) ? lg[j] : -1e30f;

    for (int t = 1; t < L_; t++) {
        float v[T_];
#pragma unroll
        for (int i = 0; i < T_; i++)
            v[i] = __shfl_sync(0xffffffffu, prev, i) + trC[i];

        float mv[6]; int mi[6];
#pragma unroll
        for (int p = 0; p < 5; p++) {
            bool sel = v[2 * p + 1] > v[2 * p];
            mv[p] = sel ? v[2 * p + 1] : v[2 * p];
            mi[p] = sel ? 2 * p + 1 : 2 * p;
        }
        mv[5] = v[10]; mi[5] = 10;
        float nv[3]; int ni[3];
#pragma unroll
        for (int p = 0; p < 3; p++) {
            bool sel = mv[2 * p + 1] > mv[2 * p];
            nv[p] = sel ? mv[2 * p + 1] : mv[2 * p];
            ni[p] = sel ? mi[2 * p + 1] : mi[2 * p];
        }
        bool s01 = nv[1] > nv[0];
        float pv = s01 ? nv[1] : nv[0];
        int   pi = s01 ? ni[1] : ni[0];
        bool sf_ = nv[2] > pv;
        float best = sf_ ? nv[2] : pv;
        int   bp   = sf_ ? ni[2] : pi;

        prev = lg[t * T_ + jj] + best;
        if (j < T_) bps[(t - 1) * T_ + j] = (unsigned char)bp;
    }

    __syncwarp();
    if (j == 0) {
        float best = prev; int tag = 0;
#pragma unroll
        for (int i = 1; i < T_; i++) {
            float vi = __shfl_sync(0x7ffu, prev, i);
            if (vi > best) { best = vi; tag = i; }
        }
        if (scores) scores[b] = best;
        if (paths) {
            paths[b * L_ + (L_ - 1)] = (float)tag;
            int st = tag;
            for (int t = L_ - 2; t >= 0; t--) {
                st = bps[t * T_ + st];
                paths[b * L_ + t] = (float)st;
            }
        }
    } else if (j < T_) {
#pragma unroll
        for (int i = 1; i < T_; i++) __shfl_sync(0x7ffu, prev, i);
    }
}

// ---------------------------------------------------------------------------
// Launcher
// ---------------------------------------------------------------------------
extern "C" void kernel_launch(void* const* d_in, const int* in_sizes, int n_in,
                              void* d_out, int out_size)
{
    const int*   sent  = (const int*)  d_in[0];
    const float* emb   = (const float*)d_in[1];
    const float* Wih_f = (const float*)d_in[2];
    const float* Whh_f = (const float*)d_in[3];
    const float* b_f   = (const float*)d_in[4];
    const float* Wih_b = (const float*)d_in[5];
    const float* Whh_b = (const float*)d_in[6];
    const float* b_b   = (const float*)d_in[7];
    const float* Wout  = (const float*)d_in[8];
    const float* bout  = (const float*)d_in[9];
    const float* trans = (const float*)d_in[10];
    const float* h0    = (const float*)d_in[11];
    const float* c0    = (const float*)d_in[12];

    float* out = (float*)d_out;
    float* scores = nullptr;
    float* paths  = nullptr;
    if (out_size >= B_ + B_ * L_)      { scores = out; paths = out + B_; }
    else if (out_size == B_ * L_)      { paths = out; }
    else                               { scores = out; }

    // 1. init h buffers + counters
    init_kernel<<<128, 256>>>(h0);

    // 2. fused producer + recurrence (128 co-resident blocks, ~176 KB smem)
    const int smem_bytes = SMEM_FLOATS * (int)sizeof(float);
    cudaFuncSetAttribute(lstm_kernel, cudaFuncAttributeMaxDynamicSharedMemorySize, smem_bytes);
    lstm_kernel<<<NBLK_LSTM, 512, smem_bytes>>>(c0, Whh_f, Whh_b,
                                                sent, emb, Wih_f, b_f, Wih_b, b_b);

    // 3. output projection (256 blocks x 128 threads)
    logits_kernel<<<M_ / 128, 128>>>(Wout, bout);

    // 4. Viterbi decode + write outputs
    viterbi_kernel<<<B_, 32>>>(trans, scores, paths);
}